// round 9
// baseline (speedup 1.0000x reference)
#include <cuda_runtime.h>

#define B_TOTAL  8192
#define T_STEPS  512
#define HID      128
#define BM       64      // batch rows per CTA (32 row-pairs)
#define NPAIR    32
#define NKQ      32      // K = 128 exactly (x/bias folded into acc init)
#define PITCHF   256     // floats per pair-row (128 k's pair-interleaved)
#define NTHREADS 256
#define ALPHA_C  0.2f
#define BETA_C   0.7f

typedef unsigned long long u64;

__device__ __forceinline__ u64 pack2(float lo, float hi) {
    u64 r; asm("mov.b64 %0, {%1, %2};" : "=l"(r) : "f"(lo), "f"(hi)); return r;
}
__device__ __forceinline__ void unpack2(u64 v, float& lo, float& hi) {
    asm("mov.b64 {%0, %1}, %2;" : "=f"(lo), "=f"(hi) : "l"(v));
}
// c += a*b (packed f32x2 -> SASS FFMA2)
__device__ __forceinline__ void fma2(u64& c, u64 a, u64 b) {
    asm("fma.rn.f32x2 %0, %1, %2, %0;" : "+l"(c) : "l"(a), "l"(b));
}
// c = c*b + h (packed)
__device__ __forceinline__ void fma2s(u64& c, u64 b, u64 h) {
    asm("fma.rn.f32x2 %0, %0, %1, %2;" : "+l"(c) : "l"(b), "l"(h));
}
// HW tanh (MUFU.TANH)
__device__ __forceinline__ float tanh_hw(float x) {
    float y; asm("tanh.approx.f32 %0, %1;" : "=f"(y) : "f"(x)); return y;
}

extern __shared__ float smem[];

__global__ __launch_bounds__(NTHREADS, 1)
void rnn_kernel(const float* __restrict__ input,   // (B, T, 2)
                const float* __restrict__ W_rec,   // (130, 128)
                const float* __restrict__ b_rec,   // (128)
                const float* __restrict__ W_out,   // (128, 1)
                const float* __restrict__ b_out,   // (1)
                float* __restrict__ out)           // (B)
{
    // layout: sW[128*128] | sA0[32*256] | sA1[32*256] | sX0[128] | sX1[128] | sRed[64]
    float* sW  = smem;
    float* sA0 = sW  + 128 * HID;
    float* sA1 = sA0 + NPAIR * PITCHF;
    float* sX0 = sA1 + NPAIR * PITCHF;
    float* sX1 = sX0 + 4 * NPAIR;
    float* sRed = sX1 + 4 * NPAIR;

    const int tid = threadIdx.x;
    const int cg  = tid & 31;   // lane: 4 n-columns
    const int rg  = tid >> 5;   // warp: 4 row-pairs (8 rows)
    const int n0  = cg * 4;
    const int rgP = rg * 4;
    const int rowBase = rg * 8;
    const int bBase   = blockIdx.x * BM;

    // W hidden part only: sW[k][n] = W_rec[k+2][n]
    for (int idx = tid; idx < 128 * HID; idx += NTHREADS)
        sW[idx] = W_rec[(idx >> 7) * HID + 256 + (idx & 127)];
    // Zero h buffer 0 (h_{-1} = 0)
    for (int idx = tid; idx < NPAIR * PITCHF; idx += NTHREADS) sA0[idx] = 0.0f;

    float wout[4];
    u64   bias2[4], wx0d[4], wx1d[4];
    #pragma unroll
    for (int n = 0; n < 4; n++) {
        float b = b_rec[n0 + n];
        bias2[n] = pack2(b, b);
        float w0 = W_rec[n0 + n];          // W_rec row 0 (x0)
        float w1 = W_rec[HID + n0 + n];    // W_rec row 1 (x1)
        wx0d[n] = pack2(w0, w0);
        wx1d[n] = pack2(w1, w1);
        wout[n] = W_out[n0 + n];
    }
    const float bout = b_out[0];
    const u64 beta2 = pack2(BETA_C, BETA_C);

    // x loader: threads 0..63, one batch row each
    const long long rowOff = (long long)(bBase + (tid & 63)) * T_STEPS * 2;
    float  racc = 0.0f, prevx0 = 0.0f;
    float2 xcur = make_float2(0.0f, 0.0f);
    if (tid < BM) {
        xcur = *(const float2*)(input + rowOff);       // x_0 -> buffer 0
        const int p = tid >> 1, par = tid & 1;
        sX0[p * 4 + par]     = xcur.x;
        sX0[p * 4 + 2 + par] = xcur.y;
    }
    __syncthreads();

    u64 hacc2[4][4];   // beta-weighted sum of h, packed {row 2j, row 2j+1}
    #pragma unroll
    for (int j = 0; j < 4; j++)
        #pragma unroll
        for (int nn = 0; nn < 4; nn++) hacc2[j][nn] = 0ULL;

    float* curA = sA0; float* nxtA = sA1;
    float* curX = sX0; float* nxtX = sX1;

    for (int t = 0; t < T_STEPS; ++t) {
        // Prefetch x_{t+1}
        float2 xnext = make_float2(0.0f, 0.0f);
        if (tid < BM && t + 1 < T_STEPS)
            xnext = *(const float2*)(input + rowOff + (long long)(t + 1) * 2);

        // acc init: bias + x0*Wx0 + x1*Wx1 (x via broadcast LDS.128 per pair)
        u64 acc2[4][4];
        #pragma unroll
        for (int j = 0; j < 4; j++) {
            float4 xp = *(const float4*)(curX + (rgP + j) * 4); // {x0e,x0o,x1e,x1o}
            u64 x0p = pack2(xp.x, xp.y);
            u64 x1p = pack2(xp.z, xp.w);
            #pragma unroll
            for (int nn = 0; nn < 4; nn++) {
                u64 a = bias2[nn];
                fma2(a, x0p, wx0d[nn]);
                fma2(a, x1p, wx1d[nn]);
                acc2[j][nn] = a;
            }
        }

        // ---- software-pipelined GEMM over 32 kq ----
        u64    aA[4][4], aB[4][4];
        float4 wA[4],    wB[4];

        // prologue: load kq = 0 into A buffers
        #pragma unroll
        for (int j = 0; j < 4; j++) {
            const float* base = curA + (rgP + j) * PITCHF;
            ulonglong2 lo = *(const ulonglong2*)(base);
            ulonglong2 hi = *(const ulonglong2*)(base + 4);
            aA[j][0] = lo.x; aA[j][1] = lo.y; aA[j][2] = hi.x; aA[j][3] = hi.y;
        }
        #pragma unroll
        for (int kk = 0; kk < 4; kk++)
            wA[kk] = *(const float4*)(sW + kk * HID + n0);

        #pragma unroll 2
        for (int kq = 0; kq < NKQ; kq += 2) {
            // prefetch kq+1 into B (always in-bounds: kq+1 <= 31)
            #pragma unroll
            for (int j = 0; j < 4; j++) {
                const float* base = curA + (rgP + j) * PITCHF + 8 * (kq + 1);
                ulonglong2 lo = *(const ulonglong2*)(base);
                ulonglong2 hi = *(const ulonglong2*)(base + 4);
                aB[j][0] = lo.x; aB[j][1] = lo.y; aB[j][2] = hi.x; aB[j][3] = hi.y;
            }
            #pragma unroll
            for (int kk = 0; kk < 4; kk++)
                wB[kk] = *(const float4*)(sW + (4 * (kq + 1) + kk) * HID + n0);

            // compute kq (A buffers)
            #pragma unroll
            for (int kk = 0; kk < 4; kk++) {
                u64 wd[4];
                wd[0] = pack2(wA[kk].x, wA[kk].x);
                wd[1] = pack2(wA[kk].y, wA[kk].y);
                wd[2] = pack2(wA[kk].z, wA[kk].z);
                wd[3] = pack2(wA[kk].w, wA[kk].w);
                #pragma unroll
                for (int j = 0; j < 4; j++) {
                    fma2(acc2[j][0], aA[j][kk], wd[0]);
                    fma2(acc2[j][1], aA[j][kk], wd[1]);
                    fma2(acc2[j][2], aA[j][kk], wd[2]);
                    fma2(acc2[j][3], aA[j][kk], wd[3]);
                }
            }

            // prefetch kq+2 into A (kq=30 -> reads 32 floats past row end:
            // lands in the next smem buffer — allocated, values unused)
            #pragma unroll
            for (int j = 0; j < 4; j++) {
                const float* base = curA + (rgP + j) * PITCHF + 8 * (kq + 2);
                ulonglong2 lo = *(const ulonglong2*)(base);
                ulonglong2 hi = *(const ulonglong2*)(base + 4);
                aA[j][0] = lo.x; aA[j][1] = lo.y; aA[j][2] = hi.x; aA[j][3] = hi.y;
            }
            if (kq + 2 < NKQ) {
                #pragma unroll
                for (int kk = 0; kk < 4; kk++)
                    wA[kk] = *(const float4*)(sW + (4 * (kq + 2) + kk) * HID + n0);
            }

            // compute kq+1 (B buffers)
            #pragma unroll
            for (int kk = 0; kk < 4; kk++) {
                u64 wd[4];
                wd[0] = pack2(wB[kk].x, wB[kk].x);
                wd[1] = pack2(wB[kk].y, wB[kk].y);
                wd[2] = pack2(wB[kk].z, wB[kk].z);
                wd[3] = pack2(wB[kk].w, wB[kk].w);
                #pragma unroll
                for (int j = 0; j < 4; j++) {
                    fma2(acc2[j][0], aB[j][kk], wd[0]);
                    fma2(acc2[j][1], aB[j][kk], wd[1]);
                    fma2(acc2[j][2], aB[j][kk], wd[2]);
                    fma2(acc2[j][3], aB[j][kk], wd[3]);
                }
            }
        }

        // tanh (HW) -> packed h; store; beta-accumulate
        #pragma unroll
        for (int j = 0; j < 4; j++) {
            u64 h2[4];
            #pragma unroll
            for (int nn = 0; nn < 4; nn++) {
                float lo, hi;
                unpack2(acc2[j][nn], lo, hi);
                h2[nn] = pack2(tanh_hw(lo), tanh_hw(hi));
            }
            float* dst = nxtA + (rgP + j) * PITCHF + 8 * cg;
            ulonglong2 s0; s0.x = h2[0]; s0.y = h2[1];
            ulonglong2 s1; s1.x = h2[2]; s1.y = h2[3];
            *(ulonglong2*)(dst)     = s0;
            *(ulonglong2*)(dst + 4) = s1;
            fma2s(hacc2[j][0], beta2, h2[0]);
            fma2s(hacc2[j][1], beta2, h2[1]);
            fma2s(hacc2[j][2], beta2, h2[2]);
            fma2s(hacc2[j][3], beta2, h2[3]);
        }

        // x_{t+1} into next buffer + resid recursion (loader threads)
        if (tid < BM) {
            const int p = tid >> 1, par = tid & 1;
            nxtX[p * 4 + par]     = xnext.x;
            nxtX[p * 4 + 2 + par] = xnext.y;
            racc = racc * BETA_C + prevx0 * prevx0;
            prevx0 = xcur.x;
            xcur = xnext;
        }
        __syncthreads();
        float* tA = curA; curA = nxtA; nxtA = tA;
        float* tX = curX; curX = nxtX; nxtX = tX;
    }

    // loader threads publish racc
    if (tid < BM) sRed[tid] = racc;
    __syncthreads();

    // One-time reduction: omega-part = hacc . W_out, butterfly over 32 lanes
    float ol[4], oh[4];
    #pragma unroll
    for (int j = 0; j < 4; j++) {
        u64 p2 = 0ULL;
        u64 w2;
        w2 = pack2(wout[0], wout[0]); fma2(p2, hacc2[j][0], w2);
        w2 = pack2(wout[1], wout[1]); fma2(p2, hacc2[j][1], w2);
        w2 = pack2(wout[2], wout[2]); fma2(p2, hacc2[j][2], w2);
        w2 = pack2(wout[3], wout[3]); fma2(p2, hacc2[j][3], w2);
        float lo, hi; unpack2(p2, lo, hi);
        #pragma unroll
        for (int s = 16; s >= 1; s >>= 1) {
            lo += __shfl_xor_sync(0xffffffffu, lo, s);
            hi += __shfl_xor_sync(0xffffffffu, hi, s);
        }
        ol[j] = lo; oh[j] = hi;
    }

    if (cg < 8) {
        const int myLocalRow = rowBase + cg;
        const int myPar = myLocalRow & 1;
        const int jj = cg >> 1;
        float om = (jj == 0) ? (myPar ? oh[0] : ol[0])
                 : (jj == 1) ? (myPar ? oh[1] : ol[1])
                 : (jj == 2) ? (myPar ? oh[2] : ol[2])
                 :             (myPar ? oh[3] : ol[3]);
        // beta^512 underflows float -> geometric sum = 1/(1-beta)
        const float geo = 1.0f / (1.0f - BETA_C);
        out[bBase + myLocalRow] = sRed[myLocalRow] * ALPHA_C + om + bout * geo;
    }
}

extern "C" void kernel_launch(void* const* d_in, const int* in_sizes, int n_in,
                              void* d_out, int out_size) {
    const float* input = (const float*)d_in[0];
    const float* W_rec = (const float*)d_in[1];
    const float* b_rec = (const float*)d_in[2];
    const float* W_out = (const float*)d_in[3];
    const float* b_out = (const float*)d_in[4];
    float* out = (float*)d_out;

    const size_t smem_bytes =
        (size_t)(128 * HID + 2 * NPAIR * PITCHF + 8 * NPAIR + BM) * sizeof(float); // ~132 KB
    cudaFuncSetAttribute(rnn_kernel, cudaFuncAttributeMaxDynamicSharedMemorySize,
                         (int)smem_bytes);

    rnn_kernel<<<B_TOTAL / BM, NTHREADS, smem_bytes>>>(input, W_rec, b_rec,
                                                       W_out, b_out, out);
    (void)in_sizes; (void)n_in; (void)out_size;
}

// round 10
// speedup vs baseline: 3.5141x; 3.5141x over previous
#include <cuda_runtime.h>
#include <cuda_fp16.h>
#include <cstdint>

#define B_TOTAL  8192
#define T_STEPS  512
#define HID      128
#define BM       64      // rows per CTA = 4 warps x 16-row M-tiles
#define NTHREADS 128
#define NKT      9       // k-tiles: 128 h + [x0,x1,bias,0..] tile
#define NNT      16      // n-tiles: N = 128
#define ALPHA_C  0.2f
#define BETA_C   0.7f

#define SB_BYTES (2 * NKT * NNT * 32 * 8)   // 73728: uint2 per (term,kt,nt,lane)

__device__ __forceinline__ float tanh_hw(float x) {
    float y; asm("tanh.approx.f32 %0, %1;" : "=f"(y) : "f"(x)); return y;
}
// pack {lo, hi} floats -> f16x2 register (cvt.rn.f16x2.f32 d, a, b : a->hi, b->lo)
__device__ __forceinline__ uint32_t f16x2(float lo, float hi) {
    uint32_t r; asm("cvt.rn.f16x2.f32 %0, %1, %2;" : "=r"(r) : "f"(hi), "f"(lo));
    return r;
}
// m16n8k16 f16 HMMA, accumulate in place
__device__ __forceinline__ void mma16816(float c[4], const uint32_t a[4],
                                         uint32_t b0, uint32_t b1) {
    asm("mma.sync.aligned.m16n8k16.row.col.f32.f16.f16.f32 "
        "{%0,%1,%2,%3}, {%4,%5,%6,%7}, {%8,%9}, {%0,%1,%2,%3};"
        : "+f"(c[0]), "+f"(c[1]), "+f"(c[2]), "+f"(c[3])
        : "r"(a[0]), "r"(a[1]), "r"(a[2]), "r"(a[3]), "r"(b0), "r"(b1));
}

extern __shared__ char smem[];

__global__ __launch_bounds__(NTHREADS, 1)
void rnn_kernel(const float* __restrict__ input,   // (B, T, 2)
                const float* __restrict__ W_rec,   // (130, 128)
                const float* __restrict__ b_rec,   // (128)
                const float* __restrict__ W_out,   // (128, 1)
                const float* __restrict__ b_out,   // (1)
                float* __restrict__ out)           // (B)
{
    uint2*  sB  = (uint2*)smem;                    // [term][kt][nt][lane] B fragments
    float2* sWP = (float2*)(smem + SB_BYTES);      // [nt][tig] wout col pairs

    const int tid  = threadIdx.x;
    const int lane = tid & 31;
    const int wid  = tid >> 5;
    const int tig  = lane & 3;     // col group within fragment
    const int gid  = lane >> 2;    // row group 0..7
    const int bBase = blockIdx.x * BM;

    // ---- build B fragments: W'(k,n) split into f16 hi (term0) + residual (term1)
    // W'(k,n): k<128 -> W_rec[k+2][n]; 128->W_rec[0][n]; 129->W_rec[1][n];
    //          130 -> b_rec[n]; else 0.
    for (int idx = tid; idx < 2 * NKT * NNT * 32; idx += NTHREADS) {
        int l    = idx & 31;
        int nt   = (idx >> 5) & 15;
        int kt   = (idx >> 9) % NKT;
        int term = (idx >> 9) / NKT;
        int n    = nt * 8 + (l >> 2);
        int kb   = kt * 16 + 2 * (l & 3);
        unsigned short hq[4];
        #pragma unroll
        for (int q = 0; q < 4; q++) {
            int k = kb + (q >> 1) * 8 + (q & 1);
            float v;
            if      (k < 128)  v = W_rec[(k + 2) * HID + n];
            else if (k == 128) v = W_rec[n];
            else if (k == 129) v = W_rec[HID + n];
            else if (k == 130) v = b_rec[n];
            else               v = 0.0f;
            __half vh = __float2half_rn(v);
            __half us = term ? __float2half_rn(v - __half2float(vh)) : vh;
            hq[q] = __half_as_ushort(us);
        }
        uint32_t b0 = (uint32_t)hq[0] | ((uint32_t)hq[1] << 16);
        uint32_t b1 = (uint32_t)hq[2] | ((uint32_t)hq[3] << 16);
        sB[idx] = make_uint2(b0, b1);
    }
    if (tid < NNT * 4) {
        int nt = tid >> 2, c = tid & 3;
        sWP[tid] = make_float2(W_out[nt * 8 + 2 * c], W_out[nt * 8 + 2 * c + 1]);
    }
    __syncthreads();

    // ---- per-thread recurrent state ----
    const int r0 = wid * 16 + gid;     // local rows r0 and r0+8
    const int r8 = r0 + 8;
    const long long off0 = (long long)(bBase + r0) * (T_STEPS * 2);
    const long long off8 = (long long)(bBase + r8) * (T_STEPS * 2);
    const float bout = b_out[0];

    float2 x0c = *(const float2*)(input + off0);   // x_0
    float2 x8c = *(const float2*)(input + off8);
    float racc0 = 0.f, racc8 = 0.f, prev0 = 0.f, prev8 = 0.f;
    float oacc0 = 0.f, oacc8 = 0.f;

    const uint32_t ONEH = 0x00003C00u;   // {lo=1.0h (bias slot), hi=0}

    uint32_t a[NKT][4];
    #pragma unroll
    for (int kt = 0; kt < 8; kt++)
        #pragma unroll
        for (int q = 0; q < 4; q++) a[kt][q] = 0u;   // h_{-1} = 0
    a[8][0] = (tig == 0) ? f16x2(x0c.x, x0c.y) : (tig == 1) ? ONEH : 0u;
    a[8][1] = (tig == 0) ? f16x2(x8c.x, x8c.y) : (tig == 1) ? ONEH : 0u;
    a[8][2] = 0u; a[8][3] = 0u;

    for (int t = 0; t < T_STEPS; ++t) {
        float2 x0n = make_float2(0.f, 0.f), x8n = make_float2(0.f, 0.f);
        if (t + 1 < T_STEPS) {
            x0n = *(const float2*)(input + off0 + (long long)(t + 1) * 2);
            x8n = *(const float2*)(input + off8 + (long long)(t + 1) * 2);
        }

        float c[NNT][4];
        #pragma unroll
        for (int nt = 0; nt < NNT; nt++) {
            c[nt][0] = 0.f; c[nt][1] = 0.f; c[nt][2] = 0.f; c[nt][3] = 0.f;
        }

        // GEMM: 9 kt x 2 terms x 16 nt HMMA, B fragments streamed from smem
        #pragma unroll
        for (int kt = 0; kt < NKT; kt++) {
            const uint2* b0p = sB + (0 * NKT + kt) * (NNT * 32) + lane;
            const uint2* b1p = sB + (1 * NKT + kt) * (NNT * 32) + lane;
            #pragma unroll
            for (int nt = 0; nt < NNT; nt++) {
                uint2 bv = b0p[nt * 32];
                mma16816(c[nt], a[kt], bv.x, bv.y);
            }
            #pragma unroll
            for (int nt = 0; nt < NNT; nt++) {
                uint2 bv = b1p[nt * 32];
                mma16816(c[nt], a[kt], bv.x, bv.y);
            }
        }

        // epilogue: tanh -> omega partials -> repack D as next-step A fragments
        float pr0 = 0.f, pr8 = 0.f;
        #pragma unroll
        for (int nt = 0; nt < NNT; nt++) {
            float t0 = tanh_hw(c[nt][0]);
            float t1 = tanh_hw(c[nt][1]);
            float t2 = tanh_hw(c[nt][2]);
            float t3 = tanh_hw(c[nt][3]);
            float2 wp = sWP[nt * 4 + tig];
            pr0 += t0 * wp.x + t1 * wp.y;
            pr8 += t2 * wp.x + t3 * wp.y;
            const int kt = nt >> 1, hh = (nt & 1) << 1;
            a[kt][hh]     = f16x2(t0, t1);
            a[kt][hh + 1] = f16x2(t2, t3);
        }
        oacc0 = oacc0 * BETA_C + pr0;
        oacc8 = oacc8 * BETA_C + pr8;
        racc0 = racc0 * BETA_C + prev0 * prev0;  prev0 = x0c.x;
        racc8 = racc8 * BETA_C + prev8 * prev8;  prev8 = x8c.x;

        a[8][0] = (tig == 0) ? f16x2(x0n.x, x0n.y) : (tig == 1) ? ONEH : 0u;
        a[8][1] = (tig == 0) ? f16x2(x8n.x, x8n.y) : (tig == 1) ? ONEH : 0u;
        x0c = x0n; x8c = x8n;
    }

    // reduce omega across the 4 col-group lanes of each quad
    oacc0 += __shfl_xor_sync(0xffffffffu, oacc0, 1);
    oacc0 += __shfl_xor_sync(0xffffffffu, oacc0, 2);
    oacc8 += __shfl_xor_sync(0xffffffffu, oacc8, 1);
    oacc8 += __shfl_xor_sync(0xffffffffu, oacc8, 2);

    if (tig == 0) {
        const float geo = 1.0f / (1.0f - BETA_C);   // beta^512 underflows
        out[bBase + r0] = racc0 * ALPHA_C + oacc0 + bout * geo;
        out[bBase + r8] = racc8 * ALPHA_C + oacc8 + bout * geo;
    }
}

extern "C" void kernel_launch(void* const* d_in, const int* in_sizes, int n_in,
                              void* d_out, int out_size) {
    const float* input = (const float*)d_in[0];
    const float* W_rec = (const float*)d_in[1];
    const float* b_rec = (const float*)d_in[2];
    const float* W_out = (const float*)d_in[3];
    const float* b_out = (const float*)d_in[4];
    float* out = (float*)d_out;

    const size_t smem_bytes = SB_BYTES + NNT * 4 * sizeof(float2);  // 74240
    cudaFuncSetAttribute(rnn_kernel, cudaFuncAttributeMaxDynamicSharedMemorySize,
                         (int)smem_bytes);

    rnn_kernel<<<B_TOTAL / BM, NTHREADS, smem_bytes>>>(input, W_rec, b_rec,
                                                       W_out, b_out, out);
    (void)in_sizes; (void)n_in; (void)out_size;
}